// round 1
// baseline (speedup 1.0000x reference)
#include <cuda_runtime.h>
#include <math.h>

#define HIDDEN 2048
#define NH     32
#define NKV    4
#define HD     128
#define BB     2
#define SS     2048
#define QKV_O  ((NH + 2*NKV)*HD)   /* 5120 */
#define MTOK   (BB*SS)             /* 4096 */
#define SCALE  0.08838834764831845f /* 1/sqrt(128) */

/* ---------------- scratch (no allocation allowed) ---------------- */
__device__ float g_qkv[(size_t)MTOK * QKV_O];            /* [token][5120]        */
__device__ float g_q[(size_t)BB * NH * SS * HD];         /* [b][h][s][d]         */
__device__ float g_k[(size_t)BB * NKV * SS * HD];        /* [b][kh][s][d]        */
__device__ float g_v[(size_t)BB * NKV * SS * HD];        /* [b][kh][s][d]        */
__device__ float g_attn[(size_t)MTOK * NH * HD];         /* [b][s][h][d]         */

/* ---------------- GEMM: C[m][n] = sum_k A[m][k]*B[n][k] ----------------
   A: [M][K] row-major, B: [N][K] row-major, C: [M][N] row-major.
   BM=128, BN=64, BK=16, 256 threads, 8x4 microtile. */
__global__ __launch_bounds__(256) void gemm_nt(
    const float* __restrict__ A, const float* __restrict__ B,
    float* __restrict__ C, int M, int N, int K)
{
    __shared__ float As[16][128];
    __shared__ float Bs[16][64];
    const int tid = threadIdx.x;
    const int tx = tid & 15, ty = tid >> 4;
    const int m0 = blockIdx.y << 7, n0 = blockIdx.x << 6;

    float acc[8][4];
#pragma unroll
    for (int i = 0; i < 8; ++i)
#pragma unroll
        for (int j = 0; j < 4; ++j) acc[i][j] = 0.0f;

    for (int k0 = 0; k0 < K; k0 += 16) {
#pragma unroll
        for (int t = 0; t < 2; ++t) {
            int f = tid + (t << 8);           /* 0..511 float4s of A tile */
            int row = f >> 2, kq = (f & 3) << 2;
            float4 v = *(const float4*)(A + (size_t)(m0 + row) * K + k0 + kq);
            As[kq + 0][row] = v.x; As[kq + 1][row] = v.y;
            As[kq + 2][row] = v.z; As[kq + 3][row] = v.w;
        }
        {
            int row = tid >> 2, kq = (tid & 3) << 2;
            float4 v = *(const float4*)(B + (size_t)(n0 + row) * K + k0 + kq);
            Bs[kq + 0][row] = v.x; Bs[kq + 1][row] = v.y;
            Bs[kq + 2][row] = v.z; Bs[kq + 3][row] = v.w;
        }
        __syncthreads();
#pragma unroll
        for (int kk = 0; kk < 16; ++kk) {
            float4 a0 = *(const float4*)&As[kk][ty << 3];
            float4 a1 = *(const float4*)&As[kk][(ty << 3) + 4];
            float4 bv = *(const float4*)&Bs[kk][tx << 2];
            float av[8]; float bb2[4];
            av[0]=a0.x; av[1]=a0.y; av[2]=a0.z; av[3]=a0.w;
            av[4]=a1.x; av[5]=a1.y; av[6]=a1.z; av[7]=a1.w;
            bb2[0]=bv.x; bb2[1]=bv.y; bb2[2]=bv.z; bb2[3]=bv.w;
#pragma unroll
            for (int i = 0; i < 8; ++i)
#pragma unroll
                for (int j = 0; j < 4; ++j) acc[i][j] += av[i] * bb2[j];
        }
        __syncthreads();
    }
#pragma unroll
    for (int i = 0; i < 8; ++i) {
        float4 o;
        o.x = acc[i][0]; o.y = acc[i][1]; o.z = acc[i][2]; o.w = acc[i][3];
        *(float4*)(C + (size_t)(m0 + (ty << 3) + i) * N + n0 + (tx << 2)) = o;
    }
}

/* ---------------- per-head RMSNorm + RoPE + scatter ----------------
   grid (40 slots, S, B), block 128. slots: 0-31 q, 32-35 k, 36-39 v. */
__global__ void norm_rope(
    const float* __restrict__ qkv, const int* __restrict__ pos,
    const float* __restrict__ qw, const float* __restrict__ kw,
    float* __restrict__ qo, float* __restrict__ ko, float* __restrict__ vo)
{
    const int slot = blockIdx.x, s = blockIdx.y, b = blockIdx.z;
    const int d = threadIdx.x;
    const size_t token = (size_t)b * SS + s;
    float x = qkv[token * QKV_O + (size_t)slot * HD + d];

    if (slot >= 36) {
        vo[(((size_t)b * NKV + (slot - 36)) * SS + s) * HD + d] = x;
        return;
    }

    __shared__ float red[4];
    __shared__ float xs[HD];
    __shared__ float rstd;

    float ssq = x * x;
#pragma unroll
    for (int o = 16; o; o >>= 1) ssq += __shfl_xor_sync(0xffffffffu, ssq, o);
    if ((d & 31) == 0) red[d >> 5] = ssq;
    __syncthreads();
    if (d == 0) rstd = rsqrtf((red[0] + red[1] + red[2] + red[3]) * (1.0f / HD) + 1e-6f);
    __syncthreads();

    float w = (slot < 32) ? qw[d] : kw[d];
    float xn = x * rstd * w;
    xs[d] = xn;
    __syncthreads();

    int p = pos[token];
    int j = d & 63;
    float invf = expf((float)j * (-13.815510557964274f / 64.0f)); /* theta^(-j/64) */
    float ang = (float)p * invf;
    float sn, cs;
    sincosf(ang, &sn, &cs);
    float out = (d < 64) ? (xn * cs - xs[d + 64] * sn)
                         : (xn * cs + xs[d - 64] * sn);

    if (slot < 32) qo[(((size_t)b * NH + slot) * SS + s) * HD + d] = out;
    else           ko[(((size_t)b * NKV + (slot - 32)) * SS + s) * HD + d] = out;
}

/* ---------------- fp32 flash attention (causal, GQA rep=8) ----------------
   grid (S/64, NH, B), 256 threads. BQ=BK=64.
   smem rows padded: Q/K/V stride 132, P stride 68 (<=2-way conflicts). */
#define BQT 64
#define BKT 64
#define TSTR 132
#define PSTR 68
#define FLASH_SMEM ((3 * BQT * TSTR + BQT * PSTR) * 4)   /* 118784 B */

__global__ __launch_bounds__(256, 1) void flash_fwd(
    const float* __restrict__ Qb, const float* __restrict__ Kb,
    const float* __restrict__ Vb, float* __restrict__ Ob)
{
    extern __shared__ float sm[];
    float* Qs = sm;
    float* Ks = Qs + BQT * TSTR;
    float* Vs = Ks + BQT * TSTR;
    float* Ps = Vs + BQT * TSTR;

    const int tid = threadIdx.x;
    const int tx = tid & 15, ty = tid >> 4;
    const int tx4 = tx << 2, ty4 = ty << 2;
    const int qt = blockIdx.x, h = blockIdx.y, b = blockIdx.z;
    const int q0 = qt * BQT;
    const int kh = h >> 3;

    const float* Qg = Qb + (((size_t)b * NH + h) * SS + q0) * HD;
    const float* Kg0 = Kb + (((size_t)b * NKV + kh) * SS) * HD;
    const float* Vg0 = Vb + (((size_t)b * NKV + kh) * SS) * HD;

    /* load Q tile (pre-scaled) */
    for (int f = tid; f < BQT * HD / 4; f += 256) {
        int r = f >> 5, dq = (f & 31) << 2;
        float4 v = *(const float4*)(Qg + (size_t)r * HD + dq);
        v.x *= SCALE; v.y *= SCALE; v.z *= SCALE; v.w *= SCALE;
        *(float4*)&Qs[r * TSTR + dq] = v;
    }

    float acc[4][8];
#pragma unroll
    for (int i = 0; i < 4; ++i)
#pragma unroll
        for (int j = 0; j < 8; ++j) acc[i][j] = 0.0f;
    float mr[4], lr[4];
#pragma unroll
    for (int i = 0; i < 4; ++i) { mr[i] = -1e30f; lr[i] = 0.0f; }

    const int ntiles = qt + 1;
    for (int t = 0; t < ntiles; ++t) {
        __syncthreads();  /* prior PV reads done; also orders Q-tile writes */
        const float* Kg = Kg0 + (size_t)t * BKT * HD;
        const float* Vg = Vg0 + (size_t)t * BKT * HD;
        for (int f = tid; f < BKT * HD / 4; f += 256) {
            int r = f >> 5, dq = (f & 31) << 2;
            *(float4*)&Ks[r * TSTR + dq] = *(const float4*)(Kg + (size_t)r * HD + dq);
            *(float4*)&Vs[r * TSTR + dq] = *(const float4*)(Vg + (size_t)r * HD + dq);
        }
        __syncthreads();

        /* S = Q K^T (scaled already) */
        float sc[4][4];
#pragma unroll
        for (int i = 0; i < 4; ++i)
#pragma unroll
            for (int j = 0; j < 4; ++j) sc[i][j] = 0.0f;

        for (int d = 0; d < HD; d += 4) {
            float qv[16], kv[16];
#pragma unroll
            for (int i = 0; i < 4; ++i) {
                float4 q4 = *(const float4*)&Qs[(ty4 + i) * TSTR + d];
                qv[i*4+0]=q4.x; qv[i*4+1]=q4.y; qv[i*4+2]=q4.z; qv[i*4+3]=q4.w;
            }
#pragma unroll
            for (int j = 0; j < 4; ++j) {
                float4 k4 = *(const float4*)&Ks[(tx4 + j) * TSTR + d];
                kv[j*4+0]=k4.x; kv[j*4+1]=k4.y; kv[j*4+2]=k4.z; kv[j*4+3]=k4.w;
            }
#pragma unroll
            for (int i = 0; i < 4; ++i)
#pragma unroll
                for (int j = 0; j < 4; ++j) {
                    sc[i][j] += qv[i*4+0]*kv[j*4+0] + qv[i*4+1]*kv[j*4+1]
                              + qv[i*4+2]*kv[j*4+2] + qv[i*4+3]*kv[j*4+3];
                }
        }

        if (t == ntiles - 1) { /* diagonal tile: causal mask (k0 == q0) */
#pragma unroll
            for (int i = 0; i < 4; ++i)
#pragma unroll
                for (int j = 0; j < 4; ++j)
                    if (tx4 + j > ty4 + i) sc[i][j] = -1e30f;
        }

        /* online softmax; row group = 16 lanes sharing ty */
        float alpha[4];
#pragma unroll
        for (int i = 0; i < 4; ++i) {
            float rm = fmaxf(fmaxf(sc[i][0], sc[i][1]), fmaxf(sc[i][2], sc[i][3]));
#pragma unroll
            for (int o = 8; o; o >>= 1) rm = fmaxf(rm, __shfl_xor_sync(0xffffffffu, rm, o));
            float mn = fmaxf(mr[i], rm);
            alpha[i] = __expf(mr[i] - mn);
            float rs = 0.0f;
#pragma unroll
            for (int j = 0; j < 4; ++j) { sc[i][j] = __expf(sc[i][j] - mn); rs += sc[i][j]; }
#pragma unroll
            for (int o = 8; o; o >>= 1) rs += __shfl_xor_sync(0xffffffffu, rs, o);
            lr[i] = lr[i] * alpha[i] + rs;
            mr[i] = mn;
            float4 pv4; pv4.x = sc[i][0]; pv4.y = sc[i][1]; pv4.z = sc[i][2]; pv4.w = sc[i][3];
            *(float4*)&Ps[(ty4 + i) * PSTR + tx4] = pv4;
#pragma unroll
            for (int j = 0; j < 8; ++j) acc[i][j] *= alpha[i];
        }
        __syncthreads();

        /* O += P V ; thread owns rows ty4..+3, dims tx4..+3 and tx4+64..+67 */
        for (int c = 0; c < BKT; c += 4) {
            float pr[4][4];
#pragma unroll
            for (int i = 0; i < 4; ++i) {
                float4 p4 = *(const float4*)&Ps[(ty4 + i) * PSTR + c];
                pr[i][0]=p4.x; pr[i][1]=p4.y; pr[i][2]=p4.z; pr[i][3]=p4.w;
            }
#pragma unroll
            for (int cc = 0; cc < 4; ++cc) {
                float4 v0 = *(const float4*)&Vs[(c + cc) * TSTR + tx4];
                float4 v1 = *(const float4*)&Vs[(c + cc) * TSTR + tx4 + 64];
#pragma unroll
                for (int i = 0; i < 4; ++i) {
                    float p = pr[i][cc];
                    acc[i][0] += p * v0.x; acc[i][1] += p * v0.y;
                    acc[i][2] += p * v0.z; acc[i][3] += p * v0.w;
                    acc[i][4] += p * v1.x; acc[i][5] += p * v1.y;
                    acc[i][6] += p * v1.z; acc[i][7] += p * v1.w;
                }
            }
        }
    }

    /* epilogue: divide by l, write [b][s][h][d] for the O-proj GEMM */
#pragma unroll
    for (int i = 0; i < 4; ++i) {
        float inv = 1.0f / lr[i];
        size_t base = (((size_t)b * SS + q0 + ty4 + i) * NH + h) * HD;
        float4 o0, o1;
        o0.x = acc[i][0]*inv; o0.y = acc[i][1]*inv; o0.z = acc[i][2]*inv; o0.w = acc[i][3]*inv;
        o1.x = acc[i][4]*inv; o1.y = acc[i][5]*inv; o1.z = acc[i][6]*inv; o1.w = acc[i][7]*inv;
        *(float4*)&Ob[base + tx4]      = o0;
        *(float4*)&Ob[base + tx4 + 64] = o1;
    }
}

/* ---------------- launch ---------------- */
extern "C" void kernel_launch(void* const* d_in, const int* in_sizes, int n_in,
                              void* d_out, int out_size)
{
    const float* hidden    = (const float*)d_in[0];
    const int*   positions = (const int*)d_in[1];
    const float* w_qkv     = (const float*)d_in[2];
    const float* w_o       = (const float*)d_in[3];
    const float* qw        = (const float*)d_in[4];
    const float* kw        = (const float*)d_in[5];
    float* out = (float*)d_out;

    float *qkv, *qb, *kb, *vb, *ab;
    cudaGetSymbolAddress((void**)&qkv, g_qkv);
    cudaGetSymbolAddress((void**)&qb,  g_q);
    cudaGetSymbolAddress((void**)&kb,  g_k);
    cudaGetSymbolAddress((void**)&vb,  g_v);
    cudaGetSymbolAddress((void**)&ab,  g_attn);

    /* 1. QKV projection: [4096,2048] x [5120,2048]^T -> [4096,5120] */
    gemm_nt<<<dim3(QKV_O / 64, MTOK / 128), 256>>>(hidden, w_qkv, qkv, MTOK, QKV_O, HIDDEN);

    /* 2. RMSNorm + RoPE + scatter to [b][head][s][d] */
    norm_rope<<<dim3(40, SS, BB), 128>>>(qkv, positions, qw, kw, qb, kb, vb);

    /* 3. causal flash attention -> g_attn [b][s][h][d] */
    cudaFuncSetAttribute(flash_fwd, cudaFuncAttributeMaxDynamicSharedMemorySize, FLASH_SMEM);
    flash_fwd<<<dim3(SS / BQT, NH, BB), 256, FLASH_SMEM>>>(qb, kb, vb, ab);

    /* 4. O projection: [4096,4096] x [2048,4096]^T -> [4096,2048] */
    gemm_nt<<<dim3(HIDDEN / 64, MTOK / 128), 256>>>(ab, w_o, out, MTOK, HIDDEN, NH * HD);
}

// round 2
// speedup vs baseline: 1.5404x; 1.5404x over previous
#include <cuda_runtime.h>
#include <math.h>
#include <stdint.h>

#define HIDDEN 2048
#define NH     32
#define NKV    4
#define HD     128
#define BB     2
#define SS     2048
#define QKV_O  ((NH + 2*NKV)*HD)   /* 5120 */
#define MTOK   (BB*SS)             /* 4096 */
#define SCALE  0.08838834764831845f /* 1/sqrt(128) */

/* ---------------- scratch (no allocation allowed) ---------------- */
__device__ float g_qkv[(size_t)MTOK * QKV_O];            /* [token][5120]        */
__device__ float g_q[(size_t)BB * NH * SS * HD];         /* [b][h][s][d]         */
__device__ float g_k[(size_t)BB * NKV * SS * HD];        /* [b][kh][s][d]        */
__device__ float g_v[(size_t)BB * NKV * SS * HD];        /* [b][kh][s][d]        */
__device__ float g_attn[(size_t)MTOK * NH * HD];         /* [b][s][h][d]         */

/* ---------------- tf32 helpers ---------------- */
__device__ __forceinline__ uint32_t f2tf32(float x) {
    uint32_t r;
    asm("cvt.rna.tf32.f32 %0, %1;" : "=r"(r) : "f"(x));
    return r;
}

__device__ __forceinline__ void mma_tf32(float* c,
    uint32_t a0, uint32_t a1, uint32_t a2, uint32_t a3,
    uint32_t b0, uint32_t b1)
{
    asm volatile(
        "mma.sync.aligned.m16n8k8.row.col.f32.tf32.tf32.f32 "
        "{%0,%1,%2,%3}, {%4,%5,%6,%7}, {%8,%9}, {%0,%1,%2,%3};"
        : "+f"(c[0]), "+f"(c[1]), "+f"(c[2]), "+f"(c[3])
        : "r"(a0), "r"(a1), "r"(a2), "r"(a3), "r"(b0), "r"(b1));
}

/* ---------------- tf32 tensor-core GEMM ----------------
   C[m][n] = sum_k A[m][k]*B[n][k]; A [M][K], B [N][K], C [M][N] row-major.
   BM=BN=128, BK=32, 256 threads (8 warps, 2x4), warp tile 64x32.
   Smem stride 36 words -> fragment LDS bank = (4g+t) mod 32: conflict-free. */
__global__ __launch_bounds__(256, 1) void gemm_tf32(
    const float* __restrict__ A, const float* __restrict__ B,
    float* __restrict__ C, int M, int N, int K)
{
    __shared__ uint32_t As[128][36];
    __shared__ uint32_t Bs[128][36];

    const int tid  = threadIdx.x;
    const int lane = tid & 31, wid = tid >> 5;
    const int g = lane >> 2, t = lane & 3;
    const int wm = (wid & 1) << 6;    /* warp m offset: 0 / 64   */
    const int wn = (wid >> 1) << 5;   /* warp n offset: 0..96    */
    const int m0 = blockIdx.y << 7, n0 = blockIdx.x << 7;

    const int r0 = tid >> 3;          /* 0..31 */
    const int c0 = (tid & 7) << 2;    /* 0,4,...,28 */

    float acc[4][4][4];
#pragma unroll
    for (int mt = 0; mt < 4; ++mt)
#pragma unroll
        for (int nt = 0; nt < 4; ++nt)
#pragma unroll
            for (int i = 0; i < 4; ++i) acc[mt][nt][i] = 0.0f;

    /* prefetch first k-tile into registers */
    float4 pa[4], pb[4];
#pragma unroll
    for (int p = 0; p < 4; ++p) {
        pa[p] = *(const float4*)(A + (size_t)(m0 + r0 + 32*p) * K + c0);
        pb[p] = *(const float4*)(B + (size_t)(n0 + r0 + 32*p) * K + c0);
    }

    for (int k0 = 0; k0 < K; k0 += 32) {
        /* store prefetched tile (with rna tf32 rounding) */
#pragma unroll
        for (int p = 0; p < 4; ++p) {
            int rr = r0 + 32*p;
            As[rr][c0+0] = f2tf32(pa[p].x); As[rr][c0+1] = f2tf32(pa[p].y);
            As[rr][c0+2] = f2tf32(pa[p].z); As[rr][c0+3] = f2tf32(pa[p].w);
            Bs[rr][c0+0] = f2tf32(pb[p].x); Bs[rr][c0+1] = f2tf32(pb[p].y);
            Bs[rr][c0+2] = f2tf32(pb[p].z); Bs[rr][c0+3] = f2tf32(pb[p].w);
        }
        __syncthreads();

        /* prefetch next tile (overlaps with MMA below) */
        if (k0 + 32 < K) {
#pragma unroll
            for (int p = 0; p < 4; ++p) {
                pa[p] = *(const float4*)(A + (size_t)(m0 + r0 + 32*p) * K + k0 + 32 + c0);
                pb[p] = *(const float4*)(B + (size_t)(n0 + r0 + 32*p) * K + k0 + 32 + c0);
            }
        }

#pragma unroll
        for (int kk = 0; kk < 4; ++kk) {
            const int kb = kk << 3;
            uint32_t af[4][4], bf[4][2];
#pragma unroll
            for (int mt = 0; mt < 4; ++mt) {
                int row = wm + (mt << 4) + g;
                af[mt][0] = As[row    ][kb + t];
                af[mt][1] = As[row + 8][kb + t];
                af[mt][2] = As[row    ][kb + t + 4];
                af[mt][3] = As[row + 8][kb + t + 4];
            }
#pragma unroll
            for (int nt = 0; nt < 4; ++nt) {
                int row = wn + (nt << 3) + g;
                bf[nt][0] = Bs[row][kb + t];
                bf[nt][1] = Bs[row][kb + t + 4];
            }
#pragma unroll
            for (int mt = 0; mt < 4; ++mt)
#pragma unroll
                for (int nt = 0; nt < 4; ++nt)
                    mma_tf32(acc[mt][nt],
                             af[mt][0], af[mt][1], af[mt][2], af[mt][3],
                             bf[nt][0], bf[nt][1]);
        }
        __syncthreads();
    }

    /* epilogue: c0/c1 -> (row, 2t/2t+1), c2/c3 -> (row+8, ...) */
#pragma unroll
    for (int mt = 0; mt < 4; ++mt) {
        int row = m0 + wm + (mt << 4) + g;
#pragma unroll
        for (int nt = 0; nt < 4; ++nt) {
            int col = n0 + wn + (nt << 3) + (t << 1);
            float2 v0; v0.x = acc[mt][nt][0]; v0.y = acc[mt][nt][1];
            float2 v1; v1.x = acc[mt][nt][2]; v1.y = acc[mt][nt][3];
            *(float2*)(C + (size_t)row * N + col)       = v0;
            *(float2*)(C + (size_t)(row + 8) * N + col) = v1;
        }
    }
}

/* ---------------- per-head RMSNorm + RoPE + scatter ----------------
   grid (40 slots, S, B), block 128. slots: 0-31 q, 32-35 k, 36-39 v. */
__global__ void norm_rope(
    const float* __restrict__ qkv, const int* __restrict__ pos,
    const float* __restrict__ qw, const float* __restrict__ kw,
    float* __restrict__ qo, float* __restrict__ ko, float* __restrict__ vo)
{
    const int slot = blockIdx.x, s = blockIdx.y, b = blockIdx.z;
    const int d = threadIdx.x;
    const size_t token = (size_t)b * SS + s;
    float x = qkv[token * QKV_O + (size_t)slot * HD + d];

    if (slot >= 36) {
        vo[(((size_t)b * NKV + (slot - 36)) * SS + s) * HD + d] = x;
        return;
    }

    __shared__ float red[4];
    __shared__ float xs[HD];
    __shared__ float rstd;

    float ssq = x * x;
#pragma unroll
    for (int o = 16; o; o >>= 1) ssq += __shfl_xor_sync(0xffffffffu, ssq, o);
    if ((d & 31) == 0) red[d >> 5] = ssq;
    __syncthreads();
    if (d == 0) rstd = rsqrtf((red[0] + red[1] + red[2] + red[3]) * (1.0f / HD) + 1e-6f);
    __syncthreads();

    float w = (slot < 32) ? qw[d] : kw[d];
    float xn = x * rstd * w;
    xs[d] = xn;
    __syncthreads();

    int p = pos[token];
    int j = d & 63;
    float invf = expf((float)j * (-13.815510557964274f / 64.0f)); /* theta^(-j/64) */
    float ang = (float)p * invf;
    float sn, cs;
    sincosf(ang, &sn, &cs);
    float out = (d < 64) ? (xn * cs - xs[d + 64] * sn)
                         : (xn * cs + xs[d - 64] * sn);

    if (slot < 32) qo[(((size_t)b * NH + slot) * SS + s) * HD + d] = out;
    else           ko[(((size_t)b * NKV + (slot - 32)) * SS + s) * HD + d] = out;
}

/* ---------------- fp32 flash attention (causal, GQA rep=8) ----------------
   grid (S/64, NH, B), 256 threads. BQ=BK=64. */
#define BQT 64
#define BKT 64
#define TSTR 132
#define PSTR 68
#define FLASH_SMEM ((3 * BQT * TSTR + BQT * PSTR) * 4)   /* 118784 B */

__global__ __launch_bounds__(256, 1) void flash_fwd(
    const float* __restrict__ Qb, const float* __restrict__ Kb,
    const float* __restrict__ Vb, float* __restrict__ Ob)
{
    extern __shared__ float sm[];
    float* Qs = sm;
    float* Ks = Qs + BQT * TSTR;
    float* Vs = Ks + BQT * TSTR;
    float* Ps = Vs + BQT * TSTR;

    const int tid = threadIdx.x;
    const int tx = tid & 15, ty = tid >> 4;
    const int tx4 = tx << 2, ty4 = ty << 2;
    const int qt = blockIdx.x, h = blockIdx.y, b = blockIdx.z;
    const int q0 = qt * BQT;
    const int kh = h >> 3;

    const float* Qg = Qb + (((size_t)b * NH + h) * SS + q0) * HD;
    const float* Kg0 = Kb + (((size_t)b * NKV + kh) * SS) * HD;
    const float* Vg0 = Vb + (((size_t)b * NKV + kh) * SS) * HD;

    for (int f = tid; f < BQT * HD / 4; f += 256) {
        int r = f >> 5, dq = (f & 31) << 2;
        float4 v = *(const float4*)(Qg + (size_t)r * HD + dq);
        v.x *= SCALE; v.y *= SCALE; v.z *= SCALE; v.w *= SCALE;
        *(float4*)&Qs[r * TSTR + dq] = v;
    }

    float acc[4][8];
#pragma unroll
    for (int i = 0; i < 4; ++i)
#pragma unroll
        for (int j = 0; j < 8; ++j) acc[i][j] = 0.0f;
    float mr[4], lr[4];
#pragma unroll
    for (int i = 0; i < 4; ++i) { mr[i] = -1e30f; lr[i] = 0.0f; }

    const int ntiles = qt + 1;
    for (int t = 0; t < ntiles; ++t) {
        __syncthreads();
        const float* Kg = Kg0 + (size_t)t * BKT * HD;
        const float* Vg = Vg0 + (size_t)t * BKT * HD;
        for (int f = tid; f < BKT * HD / 4; f += 256) {
            int r = f >> 5, dq = (f & 31) << 2;
            *(float4*)&Ks[r * TSTR + dq] = *(const float4*)(Kg + (size_t)r * HD + dq);
            *(float4*)&Vs[r * TSTR + dq] = *(const float4*)(Vg + (size_t)r * HD + dq);
        }
        __syncthreads();

        float sc[4][4];
#pragma unroll
        for (int i = 0; i < 4; ++i)
#pragma unroll
            for (int j = 0; j < 4; ++j) sc[i][j] = 0.0f;

        for (int d = 0; d < HD; d += 4) {
            float qv[16], kv[16];
#pragma unroll
            for (int i = 0; i < 4; ++i) {
                float4 q4 = *(const float4*)&Qs[(ty4 + i) * TSTR + d];
                qv[i*4+0]=q4.x; qv[i*4+1]=q4.y; qv[i*4+2]=q4.z; qv[i*4+3]=q4.w;
            }
#pragma unroll
            for (int j = 0; j < 4; ++j) {
                float4 k4 = *(const float4*)&Ks[(tx4 + j) * TSTR + d];
                kv[j*4+0]=k4.x; kv[j*4+1]=k4.y; kv[j*4+2]=k4.z; kv[j*4+3]=k4.w;
            }
#pragma unroll
            for (int i = 0; i < 4; ++i)
#pragma unroll
                for (int j = 0; j < 4; ++j) {
                    sc[i][j] += qv[i*4+0]*kv[j*4+0] + qv[i*4+1]*kv[j*4+1]
                              + qv[i*4+2]*kv[j*4+2] + qv[i*4+3]*kv[j*4+3];
                }
        }

        if (t == ntiles - 1) {
#pragma unroll
            for (int i = 0; i < 4; ++i)
#pragma unroll
                for (int j = 0; j < 4; ++j)
                    if (tx4 + j > ty4 + i) sc[i][j] = -1e30f;
        }

        float alpha[4];
#pragma unroll
        for (int i = 0; i < 4; ++i) {
            float rm = fmaxf(fmaxf(sc[i][0], sc[i][1]), fmaxf(sc[i][2], sc[i][3]));
#pragma unroll
            for (int o = 8; o; o >>= 1) rm = fmaxf(rm, __shfl_xor_sync(0xffffffffu, rm, o));
            float mn = fmaxf(mr[i], rm);
            alpha[i] = __expf(mr[i] - mn);
            float rs = 0.0f;
#pragma unroll
            for (int j = 0; j < 4; ++j) { sc[i][j] = __expf(sc[i][j] - mn); rs += sc[i][j]; }
#pragma unroll
            for (int o = 8; o; o >>= 1) rs += __shfl_xor_sync(0xffffffffu, rs, o);
            lr[i] = lr[i] * alpha[i] + rs;
            mr[i] = mn;
            float4 pv4; pv4.x = sc[i][0]; pv4.y = sc[i][1]; pv4.z = sc[i][2]; pv4.w = sc[i][3];
            *(float4*)&Ps[(ty4 + i) * PSTR + tx4] = pv4;
#pragma unroll
            for (int j = 0; j < 8; ++j) acc[i][j] *= alpha[i];
        }
        __syncthreads();

        for (int c = 0; c < BKT; c += 4) {
            float pr[4][4];
#pragma unroll
            for (int i = 0; i < 4; ++i) {
                float4 p4 = *(const float4*)&Ps[(ty4 + i) * PSTR + c];
                pr[i][0]=p4.x; pr[i][1]=p4.y; pr[i][2]=p4.z; pr[i][3]=p4.w;
            }
#pragma unroll
            for (int cc = 0; cc < 4; ++cc) {
                float4 v0 = *(const float4*)&Vs[(c + cc) * TSTR + tx4];
                float4 v1 = *(const float4*)&Vs[(c + cc) * TSTR + tx4 + 64];
#pragma unroll
                for (int i = 0; i < 4; ++i) {
                    float p = pr[i][cc];
                    acc[i][0] += p * v0.x; acc[i][1] += p * v0.y;
                    acc[i][2] += p * v0.z; acc[i][3] += p * v0.w;
                    acc[i][4] += p * v1.x; acc[i][5] += p * v1.y;
                    acc[i][6] += p * v1.z; acc[i][7] += p * v1.w;
                }
            }
        }
    }

#pragma unroll
    for (int i = 0; i < 4; ++i) {
        float inv = 1.0f / lr[i];
        size_t base = (((size_t)b * SS + q0 + ty4 + i) * NH + h) * HD;
        float4 o0, o1;
        o0.x = acc[i][0]*inv; o0.y = acc[i][1]*inv; o0.z = acc[i][2]*inv; o0.w = acc[i][3]*inv;
        o1.x = acc[i][4]*inv; o1.y = acc[i][5]*inv; o1.z = acc[i][6]*inv; o1.w = acc[i][7]*inv;
        *(float4*)&Ob[base + tx4]      = o0;
        *(float4*)&Ob[base + tx4 + 64] = o1;
    }
}

/* ---------------- launch ---------------- */
extern "C" void kernel_launch(void* const* d_in, const int* in_sizes, int n_in,
                              void* d_out, int out_size)
{
    const float* hidden    = (const float*)d_in[0];
    const int*   positions = (const int*)d_in[1];
    const float* w_qkv     = (const float*)d_in[2];
    const float* w_o       = (const float*)d_in[3];
    const float* qw        = (const float*)d_in[4];
    const float* kw        = (const float*)d_in[5];
    float* out = (float*)d_out;

    float *qkv, *qb, *kb, *vb, *ab;
    cudaGetSymbolAddress((void**)&qkv, g_qkv);
    cudaGetSymbolAddress((void**)&qb,  g_q);
    cudaGetSymbolAddress((void**)&kb,  g_k);
    cudaGetSymbolAddress((void**)&vb,  g_v);
    cudaGetSymbolAddress((void**)&ab,  g_attn);

    /* 1. QKV projection: [4096,2048] x [5120,2048]^T -> [4096,5120] */
    gemm_tf32<<<dim3(QKV_O / 128, MTOK / 128), 256>>>(hidden, w_qkv, qkv, MTOK, QKV_O, HIDDEN);

    /* 2. RMSNorm + RoPE + scatter */
    norm_rope<<<dim3(40, SS, BB), 128>>>(qkv, positions, qw, kw, qb, kb, vb);

    /* 3. causal flash attention -> g_attn [b][s][h][d] */
    cudaFuncSetAttribute(flash_fwd, cudaFuncAttributeMaxDynamicSharedMemorySize, FLASH_SMEM);
    flash_fwd<<<dim3(SS / BQT, NH, BB), 256, FLASH_SMEM>>>(qb, kb, vb, ab);

    /* 4. O projection: [4096,4096] x [2048,4096]^T -> [4096,2048] */
    gemm_tf32<<<dim3(HIDDEN / 128, MTOK / 128), 256>>>(ab, w_o, out, MTOK, HIDDEN, NH * HD);
}

// round 3
// speedup vs baseline: 3.6784x; 2.3879x over previous
#include <cuda_runtime.h>
#include <math.h>
#include <stdint.h>

#define HIDDEN 2048
#define NH     32
#define NKV    4
#define HD     128
#define BB     2
#define SS     2048
#define QKV_O  ((NH + 2*NKV)*HD)   /* 5120 */
#define MTOK   (BB*SS)             /* 4096 */
#define SCALE  0.08838834764831845f /* 1/sqrt(128) */

/* ---------------- scratch ---------------- */
__device__ float g_qkv[(size_t)MTOK * QKV_O];
__device__ float g_q[(size_t)BB * NH * SS * HD];
__device__ float g_k[(size_t)BB * NKV * SS * HD];
__device__ float g_v[(size_t)BB * NKV * SS * HD];
__device__ float g_attn[(size_t)MTOK * NH * HD];

/* ---------------- tf32 helpers ---------------- */
__device__ __forceinline__ uint32_t f2tf32(float x) {
    uint32_t r;
    asm("cvt.rna.tf32.f32 %0, %1;" : "=r"(r) : "f"(x));
    return r;
}

__device__ __forceinline__ void mma_tf32(float* c,
    uint32_t a0, uint32_t a1, uint32_t a2, uint32_t a3,
    uint32_t b0, uint32_t b1)
{
    asm volatile(
        "mma.sync.aligned.m16n8k8.row.col.f32.tf32.tf32.f32 "
        "{%0,%1,%2,%3}, {%4,%5,%6,%7}, {%8,%9}, {%0,%1,%2,%3};"
        : "+f"(c[0]), "+f"(c[1]), "+f"(c[2]), "+f"(c[3])
        : "r"(a0), "r"(a1), "r"(a2), "r"(a3), "r"(b0), "r"(b1));
}

/* ---------------- tf32 tensor-core GEMM (unchanged from R2) ---------------- */
__global__ __launch_bounds__(256, 1) void gemm_tf32(
    const float* __restrict__ A, const float* __restrict__ B,
    float* __restrict__ C, int M, int N, int K)
{
    __shared__ uint32_t As[128][36];
    __shared__ uint32_t Bs[128][36];

    const int tid  = threadIdx.x;
    const int lane = tid & 31, wid = tid >> 5;
    const int g = lane >> 2, t = lane & 3;
    const int wm = (wid & 1) << 6;
    const int wn = (wid >> 1) << 5;
    const int m0 = blockIdx.y << 7, n0 = blockIdx.x << 7;

    const int r0 = tid >> 3;
    const int c0 = (tid & 7) << 2;

    float acc[4][4][4];
#pragma unroll
    for (int mt = 0; mt < 4; ++mt)
#pragma unroll
        for (int nt = 0; nt < 4; ++nt)
#pragma unroll
            for (int i = 0; i < 4; ++i) acc[mt][nt][i] = 0.0f;

    float4 pa[4], pb[4];
#pragma unroll
    for (int p = 0; p < 4; ++p) {
        pa[p] = *(const float4*)(A + (size_t)(m0 + r0 + 32*p) * K + c0);
        pb[p] = *(const float4*)(B + (size_t)(n0 + r0 + 32*p) * K + c0);
    }

    for (int k0 = 0; k0 < K; k0 += 32) {
#pragma unroll
        for (int p = 0; p < 4; ++p) {
            int rr = r0 + 32*p;
            As[rr][c0+0] = f2tf32(pa[p].x); As[rr][c0+1] = f2tf32(pa[p].y);
            As[rr][c0+2] = f2tf32(pa[p].z); As[rr][c0+3] = f2tf32(pa[p].w);
            Bs[rr][c0+0] = f2tf32(pb[p].x); Bs[rr][c0+1] = f2tf32(pb[p].y);
            Bs[rr][c0+2] = f2tf32(pb[p].z); Bs[rr][c0+3] = f2tf32(pb[p].w);
        }
        __syncthreads();

        if (k0 + 32 < K) {
#pragma unroll
            for (int p = 0; p < 4; ++p) {
                pa[p] = *(const float4*)(A + (size_t)(m0 + r0 + 32*p) * K + k0 + 32 + c0);
                pb[p] = *(const float4*)(B + (size_t)(n0 + r0 + 32*p) * K + k0 + 32 + c0);
            }
        }

#pragma unroll
        for (int kk = 0; kk < 4; ++kk) {
            const int kb = kk << 3;
            uint32_t af[4][4], bf[4][2];
#pragma unroll
            for (int mt = 0; mt < 4; ++mt) {
                int row = wm + (mt << 4) + g;
                af[mt][0] = As[row    ][kb + t];
                af[mt][1] = As[row + 8][kb + t];
                af[mt][2] = As[row    ][kb + t + 4];
                af[mt][3] = As[row + 8][kb + t + 4];
            }
#pragma unroll
            for (int nt = 0; nt < 4; ++nt) {
                int row = wn + (nt << 3) + g;
                bf[nt][0] = Bs[row][kb + t];
                bf[nt][1] = Bs[row][kb + t + 4];
            }
#pragma unroll
            for (int mt = 0; mt < 4; ++mt)
#pragma unroll
                for (int nt = 0; nt < 4; ++nt)
                    mma_tf32(acc[mt][nt],
                             af[mt][0], af[mt][1], af[mt][2], af[mt][3],
                             bf[nt][0], bf[nt][1]);
        }
        __syncthreads();
    }

#pragma unroll
    for (int mt = 0; mt < 4; ++mt) {
        int row = m0 + wm + (mt << 4) + g;
#pragma unroll
        for (int nt = 0; nt < 4; ++nt) {
            int col = n0 + wn + (nt << 3) + (t << 1);
            float2 v0; v0.x = acc[mt][nt][0]; v0.y = acc[mt][nt][1];
            float2 v1; v1.x = acc[mt][nt][2]; v1.y = acc[mt][nt][3];
            *(float2*)(C + (size_t)row * N + col)       = v0;
            *(float2*)(C + (size_t)(row + 8) * N + col) = v1;
        }
    }
}

/* ---------------- per-head RMSNorm + RoPE + scatter (unchanged) ------------ */
__global__ void norm_rope(
    const float* __restrict__ qkv, const int* __restrict__ pos,
    const float* __restrict__ qw, const float* __restrict__ kw,
    float* __restrict__ qo, float* __restrict__ ko, float* __restrict__ vo)
{
    const int slot = blockIdx.x, s = blockIdx.y, b = blockIdx.z;
    const int d = threadIdx.x;
    const size_t token = (size_t)b * SS + s;
    float x = qkv[token * QKV_O + (size_t)slot * HD + d];

    if (slot >= 36) {
        vo[(((size_t)b * NKV + (slot - 36)) * SS + s) * HD + d] = x;
        return;
    }

    __shared__ float red[4];
    __shared__ float xs[HD];
    __shared__ float rstd;

    float ssq = x * x;
#pragma unroll
    for (int o = 16; o; o >>= 1) ssq += __shfl_xor_sync(0xffffffffu, ssq, o);
    if ((d & 31) == 0) red[d >> 5] = ssq;
    __syncthreads();
    if (d == 0) rstd = rsqrtf((red[0] + red[1] + red[2] + red[3]) * (1.0f / HD) + 1e-6f);
    __syncthreads();

    float w = (slot < 32) ? qw[d] : kw[d];
    float xn = x * rstd * w;
    xs[d] = xn;
    __syncthreads();

    int p = pos[token];
    int j = d & 63;
    float invf = expf((float)j * (-13.815510557964274f / 64.0f));
    float ang = (float)p * invf;
    float sn, cs;
    sincosf(ang, &sn, &cs);
    float out = (d < 64) ? (xn * cs - xs[d + 64] * sn)
                         : (xn * cs + xs[d - 64] * sn);

    if (slot < 32) qo[(((size_t)b * NH + slot) * SS + s) * HD + d] = out;
    else           ko[(((size_t)b * NKV + (slot - 32)) * SS + s) * HD + d] = out;
}

/* ---------------- tf32 tensor-core flash attention ----------------
   BQ=128, BK=64, 8 warps; warp w owns Q rows [16w,16w+16).
   Strides: Q/K 132 (row-pattern LDS conflict-free), V 136 (col-pattern
   conflict-free: 136 mod 32 == 8), P 68 (per-warp private). */
#define FBQ  128
#define FBK  64
#define QSTR 132
#define KSTR 132
#define VSTR 136
#define PST2 68
#define FTC_SMEM ((FBQ*QSTR + FBK*KSTR + FBK*VSTR + 8*16*PST2) * 4) /* 171008 */

__global__ __launch_bounds__(256, 1) void flash_tc(
    const float* __restrict__ Qb, const float* __restrict__ Kb,
    const float* __restrict__ Vb, float* __restrict__ Ob)
{
    extern __shared__ uint32_t su[];
    uint32_t* Qs = su;
    uint32_t* Ks = Qs + FBQ * QSTR;
    uint32_t* Vs = Ks + FBK * KSTR;
    uint32_t* Ps = Vs + FBK * VSTR;

    const int tid = threadIdx.x;
    const int lane = tid & 31, w = tid >> 5;
    const int g = lane >> 2, t = lane & 3;
    const int qt = (gridDim.x - 1) - blockIdx.x;   /* heaviest first */
    const int h = blockIdx.y, b = blockIdx.z;
    const int q0 = qt * FBQ;
    const int kh = h >> 3;

    const float* Qg  = Qb + (((size_t)b * NH + h) * SS + q0) * HD;
    const float* Kg0 = Kb + ((size_t)b * NKV + kh) * SS * HD;
    const float* Vg0 = Vb + ((size_t)b * NKV + kh) * SS * HD;

    /* stage Q tile (scaled, tf32) */
    for (int f = tid; f < FBQ * HD / 4; f += 256) {
        int r = f >> 5, c = (f & 31) << 2;
        float4 v = *(const float4*)(Qg + (size_t)r * HD + c);
        Qs[r*QSTR+c]   = f2tf32(v.x * SCALE);
        Qs[r*QSTR+c+1] = f2tf32(v.y * SCALE);
        Qs[r*QSTR+c+2] = f2tf32(v.z * SCALE);
        Qs[r*QSTR+c+3] = f2tf32(v.w * SCALE);
    }

    float o[16][4];
#pragma unroll
    for (int dt = 0; dt < 16; ++dt)
#pragma unroll
        for (int i = 0; i < 4; ++i) o[dt][i] = 0.0f;
    float mr0 = -1e30f, mr1 = -1e30f, lr0 = 0.0f, lr1 = 0.0f;

    uint32_t* Pw = Ps + w * 16 * PST2;
    const int qrow0 = q0 + w * 16 + g;      /* rows for c0/c1; c2/c3 = +8 */
    const int wtop  = q0 + w * 16 + 15;

    const int ntiles = 2 * qt + 2;
    for (int tt = 0; tt < ntiles; ++tt) {
        __syncthreads();
        const float* Kg = Kg0 + (size_t)tt * FBK * HD;
        const float* Vg = Vg0 + (size_t)tt * FBK * HD;
        for (int f = tid; f < FBK * HD / 4; f += 256) {
            int r = f >> 5, c = (f & 31) << 2;
            float4 kv = *(const float4*)(Kg + (size_t)r * HD + c);
            Ks[r*KSTR+c]   = f2tf32(kv.x); Ks[r*KSTR+c+1] = f2tf32(kv.y);
            Ks[r*KSTR+c+2] = f2tf32(kv.z); Ks[r*KSTR+c+3] = f2tf32(kv.w);
            float4 vv = *(const float4*)(Vg + (size_t)r * HD + c);
            Vs[r*VSTR+c]   = f2tf32(vv.x); Vs[r*VSTR+c+1] = f2tf32(vv.y);
            Vs[r*VSTR+c+2] = f2tf32(vv.z); Vs[r*VSTR+c+3] = f2tf32(vv.w);
        }
        __syncthreads();

        if (wtop < tt * FBK) continue;   /* warp fully above diagonal */

        /* S = Q K^T */
        float sc[8][4];
#pragma unroll
        for (int nt = 0; nt < 8; ++nt)
#pragma unroll
            for (int i = 0; i < 4; ++i) sc[nt][i] = 0.0f;

#pragma unroll
        for (int ks = 0; ks < 16; ++ks) {
            const int kb = ks << 3;
            const int qr = (w * 16 + g) * QSTR + kb;
            uint32_t a0 = Qs[qr + t];
            uint32_t a1 = Qs[qr + 8 * QSTR + t];
            uint32_t a2 = Qs[qr + t + 4];
            uint32_t a3 = Qs[qr + 8 * QSTR + t + 4];
#pragma unroll
            for (int nt = 0; nt < 8; ++nt) {
                uint32_t b0 = Ks[(nt * 8 + g) * KSTR + kb + t];
                uint32_t b1 = Ks[(nt * 8 + g) * KSTR + kb + t + 4];
                mma_tf32(sc[nt], a0, a1, a2, a3, b0, b1);
            }
        }

        /* causal mask (only the last two tiles touch the diagonal) */
        if (tt >= ntiles - 2) {
            const int k0g = tt * FBK + 2 * t;
#pragma unroll
            for (int nt = 0; nt < 8; ++nt) {
                int kc = k0g + nt * 8;
                if (kc     > qrow0)     sc[nt][0] = -1e30f;
                if (kc + 1 > qrow0)     sc[nt][1] = -1e30f;
                if (kc     > qrow0 + 8) sc[nt][2] = -1e30f;
                if (kc + 1 > qrow0 + 8) sc[nt][3] = -1e30f;
            }
        }

        /* online softmax (rows qrow0, qrow0+8); quad shfl reduce */
        float m0 = -1e30f, m1 = -1e30f;
#pragma unroll
        for (int nt = 0; nt < 8; ++nt) {
            m0 = fmaxf(m0, fmaxf(sc[nt][0], sc[nt][1]));
            m1 = fmaxf(m1, fmaxf(sc[nt][2], sc[nt][3]));
        }
        m0 = fmaxf(m0, __shfl_xor_sync(0xffffffffu, m0, 1));
        m0 = fmaxf(m0, __shfl_xor_sync(0xffffffffu, m0, 2));
        m1 = fmaxf(m1, __shfl_xor_sync(0xffffffffu, m1, 1));
        m1 = fmaxf(m1, __shfl_xor_sync(0xffffffffu, m1, 2));
        float mn0 = fmaxf(mr0, m0), mn1 = fmaxf(mr1, m1);
        float a0r = __expf(mr0 - mn0), a1r = __expf(mr1 - mn1);
        float s0 = 0.0f, s1 = 0.0f;
#pragma unroll
        for (int nt = 0; nt < 8; ++nt) {
            sc[nt][0] = __expf(sc[nt][0] - mn0); s0 += sc[nt][0];
            sc[nt][1] = __expf(sc[nt][1] - mn0); s0 += sc[nt][1];
            sc[nt][2] = __expf(sc[nt][2] - mn1); s1 += sc[nt][2];
            sc[nt][3] = __expf(sc[nt][3] - mn1); s1 += sc[nt][3];
        }
        s0 += __shfl_xor_sync(0xffffffffu, s0, 1);
        s0 += __shfl_xor_sync(0xffffffffu, s0, 2);
        s1 += __shfl_xor_sync(0xffffffffu, s1, 1);
        s1 += __shfl_xor_sync(0xffffffffu, s1, 2);
        lr0 = lr0 * a0r + s0; mr0 = mn0;
        lr1 = lr1 * a1r + s1; mr1 = mn1;
#pragma unroll
        for (int dt = 0; dt < 16; ++dt) {
            o[dt][0] *= a0r; o[dt][1] *= a0r;
            o[dt][2] *= a1r; o[dt][3] *= a1r;
        }

        /* P -> per-warp smem (tf32) */
#pragma unroll
        for (int nt = 0; nt < 8; ++nt) {
            int c = nt * 8 + 2 * t;
            Pw[g * PST2 + c]           = f2tf32(sc[nt][0]);
            Pw[g * PST2 + c + 1]       = f2tf32(sc[nt][1]);
            Pw[(g + 8) * PST2 + c]     = f2tf32(sc[nt][2]);
            Pw[(g + 8) * PST2 + c + 1] = f2tf32(sc[nt][3]);
        }
        __syncwarp();

        /* O += P V */
#pragma unroll
        for (int ks = 0; ks < 8; ++ks) {
            const int kb = ks << 3;
            uint32_t a0 = Pw[g * PST2 + kb + t];
            uint32_t a1 = Pw[(g + 8) * PST2 + kb + t];
            uint32_t a2 = Pw[g * PST2 + kb + t + 4];
            uint32_t a3 = Pw[(g + 8) * PST2 + kb + t + 4];
#pragma unroll
            for (int dt = 0; dt < 16; ++dt) {
                uint32_t b0 = Vs[(kb + t) * VSTR + dt * 8 + g];
                uint32_t b1 = Vs[(kb + t + 4) * VSTR + dt * 8 + g];
                mma_tf32(o[dt], a0, a1, a2, a3, b0, b1);
            }
        }
        __syncwarp();
    }

    /* epilogue -> [b][s][h][d] */
    const float inv0 = 1.0f / lr0, inv1 = 1.0f / lr1;
    const size_t base0 = (((size_t)b * SS + qrow0) * NH + h) * HD;
    const size_t base1 = (((size_t)b * SS + qrow0 + 8) * NH + h) * HD;
#pragma unroll
    for (int dt = 0; dt < 16; ++dt) {
        int col = dt * 8 + 2 * t;
        float2 v0; v0.x = o[dt][0] * inv0; v0.y = o[dt][1] * inv0;
        float2 v1; v1.x = o[dt][2] * inv1; v1.y = o[dt][3] * inv1;
        *(float2*)(Ob + base0 + col) = v0;
        *(float2*)(Ob + base1 + col) = v1;
    }
}

/* ---------------- launch ---------------- */
extern "C" void kernel_launch(void* const* d_in, const int* in_sizes, int n_in,
                              void* d_out, int out_size)
{
    const float* hidden    = (const float*)d_in[0];
    const int*   positions = (const int*)d_in[1];
    const float* w_qkv     = (const float*)d_in[2];
    const float* w_o       = (const float*)d_in[3];
    const float* qw        = (const float*)d_in[4];
    const float* kw        = (const float*)d_in[5];
    float* out = (float*)d_out;

    float *qkv, *qb, *kb, *vb, *ab;
    cudaGetSymbolAddress((void**)&qkv, g_qkv);
    cudaGetSymbolAddress((void**)&qb,  g_q);
    cudaGetSymbolAddress((void**)&kb,  g_k);
    cudaGetSymbolAddress((void**)&vb,  g_v);
    cudaGetSymbolAddress((void**)&ab,  g_attn);

    gemm_tf32<<<dim3(QKV_O / 128, MTOK / 128), 256>>>(hidden, w_qkv, qkv, MTOK, QKV_O, HIDDEN);

    norm_rope<<<dim3(40, SS, BB), 128>>>(qkv, positions, qw, kw, qb, kb, vb);

    cudaFuncSetAttribute(flash_tc, cudaFuncAttributeMaxDynamicSharedMemorySize, FTC_SMEM);
    flash_tc<<<dim3(SS / FBQ, NH, BB), 256, FTC_SMEM>>>(qb, kb, vb, ab);

    gemm_tf32<<<dim3(HIDDEN / 128, MTOK / 128), 256>>>(ab, w_o, out, MTOK, HIDDEN, NH * HD);
}

// round 4
// speedup vs baseline: 3.9208x; 1.0659x over previous
#include <cuda_runtime.h>
#include <math.h>
#include <stdint.h>

#define HIDDEN 2048
#define NH     32
#define NKV    4
#define HD     128
#define BB     2
#define SS     2048
#define QKV_O  ((NH + 2*NKV)*HD)   /* 5120 */
#define MTOK   (BB*SS)             /* 4096 */
#define SCALE  0.08838834764831845f /* 1/sqrt(128) */

/* ---------------- scratch ---------------- */
__device__ float g_qkv[(size_t)MTOK * QKV_O];
__device__ float g_q[(size_t)BB * NH * SS * HD];
__device__ float g_k[(size_t)BB * NKV * SS * HD];
__device__ float g_v[(size_t)BB * NKV * SS * HD];
__device__ float g_attn[(size_t)MTOK * NH * HD];

/* ---------------- helpers ---------------- */
__device__ __forceinline__ uint32_t f2tf32(float x) {
    uint32_t r;
    asm("cvt.rna.tf32.f32 %0, %1;" : "=r"(r) : "f"(x));
    return r;
}

__device__ __forceinline__ void mma_tf32(float* c,
    uint32_t a0, uint32_t a1, uint32_t a2, uint32_t a3,
    uint32_t b0, uint32_t b1)
{
    asm volatile(
        "mma.sync.aligned.m16n8k8.row.col.f32.tf32.tf32.f32 "
        "{%0,%1,%2,%3}, {%4,%5,%6,%7}, {%8,%9}, {%0,%1,%2,%3};"
        : "+f"(c[0]), "+f"(c[1]), "+f"(c[2]), "+f"(c[3])
        : "r"(a0), "r"(a1), "r"(a2), "r"(a3), "r"(b0), "r"(b1));
}

__device__ __forceinline__ void cp16(float* smem, const float* g) {
    uint32_t s = (uint32_t)__cvta_generic_to_shared(smem);
    asm volatile("cp.async.ca.shared.global [%0], [%1], 16;" :: "r"(s), "l"(g));
}
__device__ __forceinline__ void cp_commit() {
    asm volatile("cp.async.commit_group;" ::: "memory");
}
__device__ __forceinline__ void cp_wait0() {
    asm volatile("cp.async.wait_group 0;" ::: "memory");
}

/* ---------------- tf32 GEMM, cp.async 2-stage, 2 CTA/SM ----------------
   C[m][n] = sum_k A[m][k]*B[n][k]; BM=BN=128, BK=32, 256 thr, warp 64x32.
   Smem holds raw fp32 (stride 36 words); cvt.rna at fragment load. */
#define GSTG   4608                 /* 128*36 floats per stage per matrix */
#define G_SMEM (4 * GSTG * 4)       /* 73728 B */

__global__ __launch_bounds__(256, 2) void gemm_tf32(
    const float* __restrict__ A, const float* __restrict__ B,
    float* __restrict__ C, int M, int N, int K)
{
    extern __shared__ float smf[];
    const int tid  = threadIdx.x;
    const int lane = tid & 31, wid = tid >> 5;
    const int g = lane >> 2, t = lane & 3;
    const int wm = (wid & 1) << 6;
    const int wn = (wid >> 1) << 5;
    const int m0 = blockIdx.y << 7, n0 = blockIdx.x << 7;

    const int r0 = tid >> 3;          /* 0..31 */
    const int c0 = (tid & 7) << 2;    /* 0,4,...,28 */

    float acc[4][4][4];
#pragma unroll
    for (int mt = 0; mt < 4; ++mt)
#pragma unroll
        for (int nt = 0; nt < 4; ++nt)
#pragma unroll
            for (int i = 0; i < 4; ++i) acc[mt][nt][i] = 0.0f;

    const int T = K >> 5;

    /* prologue: stage 0 */
#pragma unroll
    for (int p = 0; p < 4; ++p) {
        int rr = r0 + 32 * p;
        cp16(smf + rr * 36 + c0,            A + (size_t)(m0 + rr) * K + c0);
        cp16(smf + 2*GSTG + rr * 36 + c0,   B + (size_t)(n0 + rr) * K + c0);
    }
    cp_commit();

    for (int kt = 0; kt < T; ++kt) {
        const int s = kt & 1;
        cp_wait0();
        __syncthreads();

        if (kt + 1 < T) {
            const int s2 = (kt + 1) & 1;
            const int k0 = (kt + 1) << 5;
#pragma unroll
            for (int p = 0; p < 4; ++p) {
                int rr = r0 + 32 * p;
                cp16(smf + s2 * GSTG + rr * 36 + c0,
                     A + (size_t)(m0 + rr) * K + k0 + c0);
                cp16(smf + 2*GSTG + s2 * GSTG + rr * 36 + c0,
                     B + (size_t)(n0 + rr) * K + k0 + c0);
            }
            cp_commit();
        }

        const float* As = smf + s * GSTG;
        const float* Bs = smf + 2*GSTG + s * GSTG;
#pragma unroll
        for (int kk = 0; kk < 4; ++kk) {
            const int kb = kk << 3;
            uint32_t af[4][4], bf[4][2];
#pragma unroll
            for (int mt = 0; mt < 4; ++mt) {
                int row = wm + (mt << 4) + g;
                af[mt][0] = f2tf32(As[row * 36 + kb + t]);
                af[mt][1] = f2tf32(As[(row + 8) * 36 + kb + t]);
                af[mt][2] = f2tf32(As[row * 36 + kb + t + 4]);
                af[mt][3] = f2tf32(As[(row + 8) * 36 + kb + t + 4]);
            }
#pragma unroll
            for (int nt = 0; nt < 4; ++nt) {
                int row = wn + (nt << 3) + g;
                bf[nt][0] = f2tf32(Bs[row * 36 + kb + t]);
                bf[nt][1] = f2tf32(Bs[row * 36 + kb + t + 4]);
            }
#pragma unroll
            for (int mt = 0; mt < 4; ++mt)
#pragma unroll
                for (int nt = 0; nt < 4; ++nt)
                    mma_tf32(acc[mt][nt],
                             af[mt][0], af[mt][1], af[mt][2], af[mt][3],
                             bf[nt][0], bf[nt][1]);
        }
    }

#pragma unroll
    for (int mt = 0; mt < 4; ++mt) {
        int row = m0 + wm + (mt << 4) + g;
#pragma unroll
        for (int nt = 0; nt < 4; ++nt) {
            int col = n0 + wn + (nt << 3) + (t << 1);
            float2 v0; v0.x = acc[mt][nt][0]; v0.y = acc[mt][nt][1];
            float2 v1; v1.x = acc[mt][nt][2]; v1.y = acc[mt][nt][3];
            *(float2*)(C + (size_t)row * N + col)       = v0;
            *(float2*)(C + (size_t)(row + 8) * N + col) = v1;
        }
    }
}

/* ---------------- per-head RMSNorm + RoPE + scatter (unchanged) ------------ */
__global__ void norm_rope(
    const float* __restrict__ qkv, const int* __restrict__ pos,
    const float* __restrict__ qw, const float* __restrict__ kw,
    float* __restrict__ qo, float* __restrict__ ko, float* __restrict__ vo)
{
    const int slot = blockIdx.x, s = blockIdx.y, b = blockIdx.z;
    const int d = threadIdx.x;
    const size_t token = (size_t)b * SS + s;
    float x = qkv[token * QKV_O + (size_t)slot * HD + d];

    if (slot >= 36) {
        vo[(((size_t)b * NKV + (slot - 36)) * SS + s) * HD + d] = x;
        return;
    }

    __shared__ float red[4];
    __shared__ float xs[HD];
    __shared__ float rstd;

    float ssq = x * x;
#pragma unroll
    for (int o = 16; o; o >>= 1) ssq += __shfl_xor_sync(0xffffffffu, ssq, o);
    if ((d & 31) == 0) red[d >> 5] = ssq;
    __syncthreads();
    if (d == 0) rstd = rsqrtf((red[0] + red[1] + red[2] + red[3]) * (1.0f / HD) + 1e-6f);
    __syncthreads();

    float w = (slot < 32) ? qw[d] : kw[d];
    float xn = x * rstd * w;
    xs[d] = xn;
    __syncthreads();

    int p = pos[token];
    int j = d & 63;
    float invf = expf((float)j * (-13.815510557964274f / 64.0f));
    float ang = (float)p * invf;
    float sn, cs;
    sincosf(ang, &sn, &cs);
    float out = (d < 64) ? (xn * cs - xs[d + 64] * sn)
                         : (xn * cs + xs[d - 64] * sn);

    if (slot < 32) qo[(((size_t)b * NH + slot) * SS + s) * HD + d] = out;
    else           ko[(((size_t)b * NKV + (slot - 32)) * SS + s) * HD + d] = out;
}

/* ---------------- tf32 flash attention, 64x64 tiles, 2 CTA/SM ----------------
   4 warps, 128 threads; warp w owns Q rows [16w,16w+16).
   Smem: Q 64x132, K 64x132, V 64x136 = 102400 B -> 2 CTAs/SM.
   P (tf32 probs) aliases the K buffer: written only after a barrier that
   ends all QK reads; K restaged only after PV (top-of-loop barrier). */
#define FBQ  64
#define FBK  64
#define QSTR 132
#define KSTR 132
#define VSTR 136
#define FTC_SMEM ((FBQ*QSTR + FBK*KSTR + FBK*VSTR) * 4)  /* 102400 */

__global__ __launch_bounds__(128, 2) void flash_tc(
    const float* __restrict__ Qb, const float* __restrict__ Kb,
    const float* __restrict__ Vb, float* __restrict__ Ob)
{
    extern __shared__ uint32_t su[];
    uint32_t* Qs = su;
    uint32_t* Ks = Qs + FBQ * QSTR;
    uint32_t* Vs = Ks + FBK * KSTR;

    const int tid = threadIdx.x;
    const int lane = tid & 31, w = tid >> 5;
    const int g = lane >> 2, t = lane & 3;
    const int qt = (gridDim.x - 1) - blockIdx.x;   /* heaviest first */
    const int h = blockIdx.y, b = blockIdx.z;
    const int q0 = qt * FBQ;
    const int kh = h >> 3;

    const float* Qg  = Qb + (((size_t)b * NH + h) * SS + q0) * HD;
    const float* Kg0 = Kb + ((size_t)b * NKV + kh) * SS * HD;
    const float* Vg0 = Vb + ((size_t)b * NKV + kh) * SS * HD;

    /* stage Q tile (scaled, tf32): 64x128 */
    for (int f = tid; f < FBQ * HD / 4; f += 128) {
        int r = f >> 5, c = (f & 31) << 2;
        float4 v = *(const float4*)(Qg + (size_t)r * HD + c);
        Qs[r*QSTR+c]   = f2tf32(v.x * SCALE);
        Qs[r*QSTR+c+1] = f2tf32(v.y * SCALE);
        Qs[r*QSTR+c+2] = f2tf32(v.z * SCALE);
        Qs[r*QSTR+c+3] = f2tf32(v.w * SCALE);
    }

    float o[16][4];
#pragma unroll
    for (int dt = 0; dt < 16; ++dt)
#pragma unroll
        for (int i = 0; i < 4; ++i) o[dt][i] = 0.0f;
    float mr0 = -1e30f, mr1 = -1e30f, lr0 = 0.0f, lr1 = 0.0f;

    uint32_t* Pw = Ks + w * 16 * KSTR;      /* P aliases K buffer */
    const int qrow0 = q0 + w * 16 + g;

    const int ntiles = qt + 1;
    for (int tt = 0; tt < ntiles; ++tt) {
        __syncthreads();   /* K(P)/V free: prior tile's PV + P reads done */
        const float* Kg = Kg0 + (size_t)tt * FBK * HD;
        const float* Vg = Vg0 + (size_t)tt * FBK * HD;
        for (int f = tid; f < FBK * HD / 4; f += 128) {
            int r = f >> 5, c = (f & 31) << 2;
            float4 kv = *(const float4*)(Kg + (size_t)r * HD + c);
            Ks[r*KSTR+c]   = f2tf32(kv.x); Ks[r*KSTR+c+1] = f2tf32(kv.y);
            Ks[r*KSTR+c+2] = f2tf32(kv.z); Ks[r*KSTR+c+3] = f2tf32(kv.w);
            float4 vv = *(const float4*)(Vg + (size_t)r * HD + c);
            Vs[r*VSTR+c]   = f2tf32(vv.x); Vs[r*VSTR+c+1] = f2tf32(vv.y);
            Vs[r*VSTR+c+2] = f2tf32(vv.z); Vs[r*VSTR+c+3] = f2tf32(vv.w);
        }
        __syncthreads();

        /* S = Q K^T */
        float sc[8][4];
#pragma unroll
        for (int nt = 0; nt < 8; ++nt)
#pragma unroll
            for (int i = 0; i < 4; ++i) sc[nt][i] = 0.0f;

#pragma unroll
        for (int ks = 0; ks < 16; ++ks) {
            const int kb = ks << 3;
            const int qr = (w * 16 + g) * QSTR + kb;
            uint32_t a0 = Qs[qr + t];
            uint32_t a1 = Qs[qr + 8 * QSTR + t];
            uint32_t a2 = Qs[qr + t + 4];
            uint32_t a3 = Qs[qr + 8 * QSTR + t + 4];
#pragma unroll
            for (int nt = 0; nt < 8; ++nt) {
                uint32_t b0 = Ks[(nt * 8 + g) * KSTR + kb + t];
                uint32_t b1 = Ks[(nt * 8 + g) * KSTR + kb + t + 4];
                mma_tf32(sc[nt], a0, a1, a2, a3, b0, b1);
            }
        }

        /* causal mask: only the diagonal (last) tile */
        if (tt == ntiles - 1) {
            const int k0g = tt * FBK + 2 * t;
#pragma unroll
            for (int nt = 0; nt < 8; ++nt) {
                int kc = k0g + nt * 8;
                if (kc     > qrow0)     sc[nt][0] = -1e30f;
                if (kc + 1 > qrow0)     sc[nt][1] = -1e30f;
                if (kc     > qrow0 + 8) sc[nt][2] = -1e30f;
                if (kc + 1 > qrow0 + 8) sc[nt][3] = -1e30f;
            }
        }

        /* online softmax (rows qrow0, qrow0+8); quad shfl reduce */
        float m0 = -1e30f, m1 = -1e30f;
#pragma unroll
        for (int nt = 0; nt < 8; ++nt) {
            m0 = fmaxf(m0, fmaxf(sc[nt][0], sc[nt][1]));
            m1 = fmaxf(m1, fmaxf(sc[nt][2], sc[nt][3]));
        }
        m0 = fmaxf(m0, __shfl_xor_sync(0xffffffffu, m0, 1));
        m0 = fmaxf(m0, __shfl_xor_sync(0xffffffffu, m0, 2));
        m1 = fmaxf(m1, __shfl_xor_sync(0xffffffffu, m1, 1));
        m1 = fmaxf(m1, __shfl_xor_sync(0xffffffffu, m1, 2));
        float mn0 = fmaxf(mr0, m0), mn1 = fmaxf(mr1, m1);
        float a0r = __expf(mr0 - mn0), a1r = __expf(mr1 - mn1);
        float s0 = 0.0f, s1 = 0.0f;
#pragma unroll
        for (int nt = 0; nt < 8; ++nt) {
            sc[nt][0] = __expf(sc[nt][0] - mn0); s0 += sc[nt][0];
            sc[nt][1] = __expf(sc[nt][1] - mn0); s0 += sc[nt][1];
            sc[nt][2] = __expf(sc[nt][2] - mn1); s1 += sc[nt][2];
            sc[nt][3] = __expf(sc[nt][3] - mn1); s1 += sc[nt][3];
        }
        s0 += __shfl_xor_sync(0xffffffffu, s0, 1);
        s0 += __shfl_xor_sync(0xffffffffu, s0, 2);
        s1 += __shfl_xor_sync(0xffffffffu, s1, 1);
        s1 += __shfl_xor_sync(0xffffffffu, s1, 2);
        lr0 = lr0 * a0r + s0; mr0 = mn0;
        lr1 = lr1 * a1r + s1; mr1 = mn1;
#pragma unroll
        for (int dt = 0; dt < 16; ++dt) {
            o[dt][0] *= a0r; o[dt][1] *= a0r;
            o[dt][2] *= a1r; o[dt][3] *= a1r;
        }

        __syncthreads();   /* all QK reads of K done -> safe to write P there */

        /* P -> per-warp region inside K buffer (tf32) */
#pragma unroll
        for (int nt = 0; nt < 8; ++nt) {
            int c = nt * 8 + 2 * t;
            Pw[g * KSTR + c]           = f2tf32(sc[nt][0]);
            Pw[g * KSTR + c + 1]       = f2tf32(sc[nt][1]);
            Pw[(g + 8) * KSTR + c]     = f2tf32(sc[nt][2]);
            Pw[(g + 8) * KSTR + c + 1] = f2tf32(sc[nt][3]);
        }
        __syncwarp();

        /* O += P V */
#pragma unroll
        for (int ks = 0; ks < 8; ++ks) {
            const int kb = ks << 3;
            uint32_t a0 = Pw[g * KSTR + kb + t];
            uint32_t a1 = Pw[(g + 8) * KSTR + kb + t];
            uint32_t a2 = Pw[g * KSTR + kb + t + 4];
            uint32_t a3 = Pw[(g + 8) * KSTR + kb + t + 4];
#pragma unroll
            for (int dt = 0; dt < 16; ++dt) {
                uint32_t b0 = Vs[(kb + t) * VSTR + dt * 8 + g];
                uint32_t b1 = Vs[(kb + t + 4) * VSTR + dt * 8 + g];
                mma_tf32(o[dt], a0, a1, a2, a3, b0, b1);
            }
        }
        __syncwarp();
    }

    /* epilogue -> [b][s][h][d] */
    const float inv0 = 1.0f / lr0, inv1 = 1.0f / lr1;
    const size_t base0 = (((size_t)b * SS + qrow0) * NH + h) * HD;
    const size_t base1 = (((size_t)b * SS + qrow0 + 8) * NH + h) * HD;
#pragma unroll
    for (int dt = 0; dt < 16; ++dt) {
        int col = dt * 8 + 2 * t;
        float2 v0; v0.x = o[dt][0] * inv0; v0.y = o[dt][1] * inv0;
        float2 v1; v1.x = o[dt][2] * inv1; v1.y = o[dt][3] * inv1;
        *(float2*)(Ob + base0 + col) = v0;
        *(float2*)(Ob + base1 + col) = v1;
    }
}

/* ---------------- launch ---------------- */
extern "C" void kernel_launch(void* const* d_in, const int* in_sizes, int n_in,
                              void* d_out, int out_size)
{
    const float* hidden    = (const float*)d_in[0];
    const int*   positions = (const int*)d_in[1];
    const float* w_qkv     = (const float*)d_in[2];
    const float* w_o       = (const float*)d_in[3];
    const float* qw        = (const float*)d_in[4];
    const float* kw        = (const float*)d_in[5];
    float* out = (float*)d_out;

    float *qkv, *qb, *kb, *vb, *ab;
    cudaGetSymbolAddress((void**)&qkv, g_qkv);
    cudaGetSymbolAddress((void**)&qb,  g_q);
    cudaGetSymbolAddress((void**)&kb,  g_k);
    cudaGetSymbolAddress((void**)&vb,  g_v);
    cudaGetSymbolAddress((void**)&ab,  g_attn);

    cudaFuncSetAttribute(gemm_tf32, cudaFuncAttributeMaxDynamicSharedMemorySize, G_SMEM);
    cudaFuncSetAttribute(flash_tc, cudaFuncAttributeMaxDynamicSharedMemorySize, FTC_SMEM);

    gemm_tf32<<<dim3(QKV_O / 128, MTOK / 128), 256, G_SMEM>>>(hidden, w_qkv, qkv, MTOK, QKV_O, HIDDEN);

    norm_rope<<<dim3(40, SS, BB), 128>>>(qkv, positions, qw, kw, qb, kb, vb);

    flash_tc<<<dim3(SS / FBQ, NH, BB), 128, FTC_SMEM>>>(qb, kb, vb, ab);

    gemm_tf32<<<dim3(HIDDEN / 128, MTOK / 128), 256, G_SMEM>>>(ab, w_o, out, MTOK, HIDDEN, NH * HD);
}